// round 11
// baseline (speedup 1.0000x reference)
#include <cuda_runtime.h>
#include <math.h>
#include <stdint.h>

// Problem constants
#define BB   2
#define SS   2048
#define DM   1024
#define NH   16
#define HDIM 64

// Scratch (device globals: allocation-free)
__device__ uint32_t g_qt[BB * SS * DM];
__device__ uint32_t g_kt[BB * SS * DM];
__device__ uint32_t g_vthi[BB * NH * HDIM * SS];
__device__ uint32_t g_vtlo[BB * NH * HDIM * SS];

// ---------------------------------------------------------------------------
// Helpers
// ---------------------------------------------------------------------------
__device__ __forceinline__ void tf32_split(float x, uint32_t& hi, uint32_t& lo) {
    uint32_t xh = __float_as_uint(x) & 0xFFFFE000u;
    hi = xh;
    lo = __float_as_uint(x - __uint_as_float(xh));
}

__device__ __forceinline__ uint32_t cvt_tf32(float x) {
    uint32_t u;
    asm("cvt.rna.tf32.f32 %0, %1;" : "=r"(u) : "f"(x));
    return u;
}

__device__ __forceinline__ void mma_tf32(float* c,
                                         uint32_t a0, uint32_t a1, uint32_t a2, uint32_t a3,
                                         uint32_t b0, uint32_t b1) {
    asm volatile(
        "mma.sync.aligned.m16n8k8.row.col.f32.tf32.tf32.f32 "
        "{%0,%1,%2,%3}, {%4,%5,%6,%7}, {%8,%9}, {%0,%1,%2,%3};\n"
        : "+f"(c[0]), "+f"(c[1]), "+f"(c[2]), "+f"(c[3])
        : "r"(a0), "r"(a1), "r"(a2), "r"(a3), "r"(b0), "r"(b1));
}

__device__ __forceinline__ void cp_async16(void* smem, const void* gmem) {
    uint32_t s = (uint32_t)__cvta_generic_to_shared(smem);
    asm volatile("cp.async.ca.shared.global [%0], [%1], 16;\n" :: "r"(s), "l"(gmem));
}
__device__ __forceinline__ void cp_commit() {
    asm volatile("cp.async.commit_group;\n");
}
__device__ __forceinline__ void cp_wait1() {
    asm volatile("cp.async.wait_group 1;\n");
}
__device__ __forceinline__ void cp_wait0() {
    asm volatile("cp.async.wait_group 0;\n");
}

// ---------------------------------------------------------------------------
// Fused projection GEMMs: one launch, blockIdx.z selects {Q, K, V}.
// CTA tile 128x64, BK=16, 256 threads, warp 32x32, 3-stage cp.async pipeline.
//  z=0: Q -> tf32 out, scaled 1/32     (1-pass tf32)
//  z=1: K -> tf32 out                  (1-pass tf32)
//  z=2: V -> transposed split hi/lo    (3-pass tf32)
// ---------------------------------------------------------------------------
#define BM 128
#define BN 64
#define BK 16
#define KPAD 4
#define NSTG 3

__device__ __forceinline__ void gemm_load_stage(
    const float* __restrict__ X, const float* __restrict__ W,
    float (*As)[BK + KPAD], float (*Bs)[BK + KPAD],
    int m0, int n0, int k0, int K, int tid)
{
#pragma unroll
    for (int i = 0; i < 2; i++) {
        int f   = tid + i * 256;
        int row = f >> 2;
        int kq  = (f & 3) * 4;
        cp_async16(&As[row][kq], &X[(size_t)(m0 + row) * K + k0 + kq]);
    }
    {
        int row = tid >> 2;
        int kq  = (tid & 3) * 4;
        cp_async16(&Bs[row][kq], &W[(size_t)(n0 + row) * K + k0 + kq]);
    }
    cp_commit();
}

__global__ __launch_bounds__(256) void gemm_fused(
    const float* __restrict__ qx, const float* __restrict__ Wq, const float* __restrict__ bq,
    const float* __restrict__ kx, const float* __restrict__ Wk, const float* __restrict__ bk,
    const float* __restrict__ vx, const float* __restrict__ Wv, const float* __restrict__ bv,
    uint32_t* __restrict__ YQ, uint32_t* __restrict__ YK,
    uint32_t* __restrict__ VHI, uint32_t* __restrict__ VLO)
{
    __shared__ __align__(16) float As[NSTG][BM][BK + KPAD];
    __shared__ __align__(16) float Bs[NSTG][BN][BK + KPAD];

    const int mode = blockIdx.z;
    const float* X    = (mode == 0) ? qx : (mode == 1) ? kx : vx;
    const float* W    = (mode == 0) ? Wq : (mode == 1) ? Wk : Wv;
    const float* bias = (mode == 0) ? bq : (mode == 1) ? bk : bv;

    const int tid  = threadIdx.x;
    const int warp = tid >> 5;
    const int lane = tid & 31;
    const int wm = (warp >> 1) * 32;
    const int wn = (warp & 1) * 32;
    const int g  = lane >> 2;
    const int tg = lane & 3;
    const int m0 = blockIdx.y * BM;
    const int n0 = blockIdx.x * BN;
    const int K = DM, N = DM;
    const int NIT = K / BK;

    float c[2][4][4];
#pragma unroll
    for (int mt = 0; mt < 2; mt++)
#pragma unroll
        for (int nt = 0; nt < 4; nt++)
#pragma unroll
            for (int r = 0; r < 4; r++) c[mt][nt][r] = 0.0f;

    gemm_load_stage(X, W, As[0], Bs[0], m0, n0, 0, K, tid);
    gemm_load_stage(X, W, As[1], Bs[1], m0, n0, BK, K, tid);

    for (int it = 0; it < NIT; it++) {
        if (it + 2 < NIT) cp_wait1(); else cp_wait0();
        __syncthreads();
        if (it + 2 < NIT)
            gemm_load_stage(X, W, As[(it + 2) % NSTG], Bs[(it + 2) % NSTG],
                            m0, n0, (it + 2) * BK, K, tid);

        const int st = it % NSTG;
        if (mode < 2) {
            // 1-pass tf32
#pragma unroll
            for (int ks = 0; ks < 2; ks++) {
                const int kb = ks * 8;
                uint32_t a[2][4];
#pragma unroll
                for (int mt = 0; mt < 2; mt++) {
                    int r0 = wm + mt * 16;
                    a[mt][0] = cvt_tf32(As[st][r0 + g    ][kb + tg    ]);
                    a[mt][1] = cvt_tf32(As[st][r0 + g + 8][kb + tg    ]);
                    a[mt][2] = cvt_tf32(As[st][r0 + g    ][kb + tg + 4]);
                    a[mt][3] = cvt_tf32(As[st][r0 + g + 8][kb + tg + 4]);
                }
#pragma unroll
                for (int nt = 0; nt < 4; nt++) {
                    int nr = wn + nt * 8 + g;
                    uint32_t b0 = cvt_tf32(Bs[st][nr][kb + tg    ]);
                    uint32_t b1 = cvt_tf32(Bs[st][nr][kb + tg + 4]);
#pragma unroll
                    for (int mt = 0; mt < 2; mt++)
                        mma_tf32(c[mt][nt], a[mt][0], a[mt][1], a[mt][2], a[mt][3], b0, b1);
                }
            }
        } else {
            // 3-pass split tf32
#pragma unroll
            for (int ks = 0; ks < 2; ks++) {
                const int kb = ks * 8;
                uint32_t ahi[2][4], alo[2][4];
#pragma unroll
                for (int mt = 0; mt < 2; mt++) {
                    int r0 = wm + mt * 16;
                    tf32_split(As[st][r0 + g    ][kb + tg    ], ahi[mt][0], alo[mt][0]);
                    tf32_split(As[st][r0 + g + 8][kb + tg    ], ahi[mt][1], alo[mt][1]);
                    tf32_split(As[st][r0 + g    ][kb + tg + 4], ahi[mt][2], alo[mt][2]);
                    tf32_split(As[st][r0 + g + 8][kb + tg + 4], ahi[mt][3], alo[mt][3]);
                }
#pragma unroll
                for (int nt = 0; nt < 4; nt++) {
                    int nr = wn + nt * 8 + g;
                    uint32_t bh0, bl0, bh1, bl1;
                    tf32_split(Bs[st][nr][kb + tg    ], bh0, bl0);
                    tf32_split(Bs[st][nr][kb + tg + 4], bh1, bl1);
#pragma unroll
                    for (int mt = 0; mt < 2; mt++) {
                        mma_tf32(c[mt][nt], ahi[mt][0], ahi[mt][1], ahi[mt][2], ahi[mt][3], bh0, bh1);
                        mma_tf32(c[mt][nt], ahi[mt][0], ahi[mt][1], ahi[mt][2], ahi[mt][3], bl0, bl1);
                        mma_tf32(c[mt][nt], alo[mt][0], alo[mt][1], alo[mt][2], alo[mt][3], bh0, bh1);
                    }
                }
            }
        }
        __syncthreads();
    }

    if (mode < 2) {
        uint32_t* Y = (mode == 0) ? YQ : YK;
        const float oscale = (mode == 0) ? 0.03125f : 1.0f;
#pragma unroll
        for (int mt = 0; mt < 2; mt++) {
#pragma unroll
            for (int nt = 0; nt < 4; nt++) {
                int m = m0 + wm + mt * 16 + g;
                int n = n0 + wn + nt * 8 + tg * 2;
                float b0 = bias[n];
                float b1 = bias[n + 1];
                Y[(size_t)m * N + n]           = cvt_tf32((c[mt][nt][0] + b0) * oscale);
                Y[(size_t)m * N + n + 1]       = cvt_tf32((c[mt][nt][1] + b1) * oscale);
                Y[(size_t)(m + 8) * N + n]     = cvt_tf32((c[mt][nt][2] + b0) * oscale);
                Y[(size_t)(m + 8) * N + n + 1] = cvt_tf32((c[mt][nt][3] + b1) * oscale);
            }
        }
    } else {
        // Transposed + split epilogue: m=(b,s), n=(h,d) -> [((b*NH+h)*HDIM+d)*SS + s]
#pragma unroll
        for (int mt = 0; mt < 2; mt++) {
#pragma unroll
            for (int nt = 0; nt < 4; nt++) {
                int m = m0 + wm + mt * 16 + g;
                int n = n0 + wn + nt * 8 + tg * 2;
                int bidx = m >> 11, s = m & 2047;
#pragma unroll
                for (int e = 0; e < 2; e++) {
                    int nn = n + e;
                    int hh = nn >> 6, dd = nn & 63;
                    size_t base = (((size_t)(bidx * NH + hh)) * HDIM + dd) * SS;
                    float bb = bias[nn];
#pragma unroll
                    for (int rr = 0; rr < 2; rr++) {
                        float y = c[mt][nt][e + 2 * rr] + bb;
                        uint32_t hi = __float_as_uint(y) & 0xFFFFE000u;  // tf32-exact
                        float lo = y - __uint_as_float(hi);
                        VHI[base + s + 8 * rr] = hi;
                        VLO[base + s + 8 * rr] = cvt_tf32(lo);
                    }
                }
            }
        }
    }
}

// ---------------------------------------------------------------------------
// Tensor-core flash attention (TF32), causal.
// CTA: 128 q-rows of one (b,h); 256 threads = 8 warps x 16 rows each.
// Identical arithmetic to R7; warp<->row mapping changed to halve per-thread
// registers (cap 128 via launch_bounds -> 2 CTAs/SM, 16 warps/SM).
// ---------------------------------------------------------------------------
#define QT 128
#define KT 64
#define PSTR 68
#define FA_SMEM ((3 * 64 * PSTR + 8 * 16 * PSTR) * (int)sizeof(uint32_t))

__global__ __launch_bounds__(256, 2) void flash_attn_tc(
    const uint32_t* __restrict__ Qt, const uint32_t* __restrict__ Kt,
    const uint32_t* __restrict__ VHI, const uint32_t* __restrict__ VLO,
    float* __restrict__ O)
{
    extern __shared__ uint32_t smu[];
    uint32_t* sK  = smu;                  // K tile  [64 keys][PSTR] (cols = d)
    uint32_t* sVh = smu + 64 * PSTR;      // V hi    [64 d][PSTR]    (cols = key)
    uint32_t* sVl = smu + 2 * 64 * PSTR;  // V lo
    uint32_t* sP  = smu + 3 * 64 * PSTR;  // per-warp P [16][PSTR]

    const int tid  = threadIdx.x;
    const int w    = tid >> 5;            // 0..7
    const int lane = tid & 31;
    const int g    = lane >> 2;
    const int tg   = lane & 3;
    const int qt   = (int)gridDim.x - 1 - (int)blockIdx.x;  // heavy tiles first
    const int h    = blockIdx.y;
    const int b    = blockIdx.z;
    const int qbase = qt * QT;
    const int rowb  = qbase + w * 16;     // this warp's first q row
    const float NEG = -1.0e30f;

    // ---- Q fragments straight from gmem (already tf32 + pre-scaled)
    const uint32_t* Qg = Qt + ((size_t)(b * SS) + qbase) * DM + h * HDIM;
    uint32_t qf[8][4];
    {
        int r0 = w * 16 + g;
#pragma unroll
        for (int ks = 0; ks < 8; ks++) {
            int cc = ks * 8 + tg;
            qf[ks][0] = Qg[(size_t)(r0    ) * DM + cc    ];
            qf[ks][1] = Qg[(size_t)(r0 + 8) * DM + cc    ];
            qf[ks][2] = Qg[(size_t)(r0    ) * DM + cc + 4];
            qf[ks][3] = Qg[(size_t)(r0 + 8) * DM + cc + 4];
        }
    }

    float of[8][4];
    float mrow[2], lrow[2];
    mrow[0] = NEG; mrow[1] = NEG;
    lrow[0] = 0.f; lrow[1] = 0.f;
#pragma unroll
    for (int nt = 0; nt < 8; nt++)
#pragma unroll
        for (int r = 0; r < 4; r++) of[nt][r] = 0.f;

    uint32_t* Pw = sP + w * 16 * PSTR;
    const int nkt = 2 * qt + 2;

    for (int kt = 0; kt < nkt; kt++) {
        __syncthreads();
        const uint32_t* Kg = Kt + ((size_t)(b * SS) + kt * KT) * DM + h * HDIM;
        size_t vbase = ((size_t)(b * NH + h) * HDIM) * SS + kt * KT;
#pragma unroll
        for (int i = 0; i < 4; i++) {
            int f = tid + i * 256;
            int row = f >> 4, c4 = (f & 15) * 4;
            *(uint4*)&sK[row * PSTR + c4]  = *(const uint4*)&Kg[(size_t)row * DM + c4];
            *(uint4*)&sVh[row * PSTR + c4] = *(const uint4*)&VHI[vbase + (size_t)row * SS + c4];
            *(uint4*)&sVl[row * PSTR + c4] = *(const uint4*)&VLO[vbase + (size_t)row * SS + c4];
        }
        __syncthreads();

        if (kt * KT > rowb + 15) continue;   // tile fully above the diagonal for this warp

        // ---- S = Q K^T (single-pass tf32)
        float s[8][4];
#pragma unroll
        for (int nt = 0; nt < 8; nt++)
#pragma unroll
            for (int r = 0; r < 4; r++) s[nt][r] = 0.f;

#pragma unroll
        for (int ks = 0; ks < 8; ks++) {
#pragma unroll
            for (int nt = 0; nt < 8; nt++) {
                int nr = nt * 8 + g;
                uint32_t b0 = sK[nr * PSTR + ks * 8 + tg    ];
                uint32_t b1 = sK[nr * PSTR + ks * 8 + tg + 4];
                mma_tf32(s[nt], qf[ks][0], qf[ks][1], qf[ks][2], qf[ks][3], b0, b1);
            }
        }

        // ---- causal mask (tiles that can cross the diagonal)
        if (kt * KT + KT - 1 > rowb) {
            int row0 = rowb + g;
#pragma unroll
            for (int nt = 0; nt < 8; nt++) {
                int col = kt * KT + nt * 8 + 2 * tg;
                if (col     > row0    ) s[nt][0] = NEG;
                if (col + 1 > row0    ) s[nt][1] = NEG;
                if (col     > row0 + 8) s[nt][2] = NEG;
                if (col + 1 > row0 + 8) s[nt][3] = NEG;
            }
        }

        // ---- online softmax + store P as tf32 (warp-private)
        {
            float rm0 = NEG, rm1 = NEG;
#pragma unroll
            for (int nt = 0; nt < 8; nt++) {
                rm0 = fmaxf(rm0, fmaxf(s[nt][0], s[nt][1]));
                rm1 = fmaxf(rm1, fmaxf(s[nt][2], s[nt][3]));
            }
#pragma unroll
            for (int d = 1; d < 4; d <<= 1) {
                rm0 = fmaxf(rm0, __shfl_xor_sync(0xffffffffu, rm0, d));
                rm1 = fmaxf(rm1, __shfl_xor_sync(0xffffffffu, rm1, d));
            }
            float mn0 = fmaxf(mrow[0], rm0);
            float mn1 = fmaxf(mrow[1], rm1);
            float corr0 = __expf(mrow[0] - mn0);
            float corr1 = __expf(mrow[1] - mn1);
            float rs0 = 0.f, rs1 = 0.f;
#pragma unroll
            for (int nt = 0; nt < 8; nt++) {
                s[nt][0] = __expf(s[nt][0] - mn0);
                s[nt][1] = __expf(s[nt][1] - mn0);
                s[nt][2] = __expf(s[nt][2] - mn1);
                s[nt][3] = __expf(s[nt][3] - mn1);
                rs0 += s[nt][0] + s[nt][1];
                rs1 += s[nt][2] + s[nt][3];
            }
#pragma unroll
            for (int d = 1; d < 4; d <<= 1) {
                rs0 += __shfl_xor_sync(0xffffffffu, rs0, d);
                rs1 += __shfl_xor_sync(0xffffffffu, rs1, d);
            }
            lrow[0] = lrow[0] * corr0 + rs0;
            lrow[1] = lrow[1] * corr1 + rs1;
            mrow[0] = mn0;
            mrow[1] = mn1;
#pragma unroll
            for (int nt = 0; nt < 8; nt++) {
                of[nt][0] *= corr0;
                of[nt][1] *= corr0;
                of[nt][2] *= corr1;
                of[nt][3] *= corr1;
            }
#pragma unroll
            for (int nt = 0; nt < 8; nt++) {
                uint2 p01 = make_uint2(cvt_tf32(s[nt][0]), cvt_tf32(s[nt][1]));
                uint2 p23 = make_uint2(cvt_tf32(s[nt][2]), cvt_tf32(s[nt][3]));
                *(uint2*)&Pw[(g    ) * PSTR + nt * 8 + 2 * tg] = p01;
                *(uint2*)&Pw[(g + 8) * PSTR + nt * 8 + 2 * tg] = p23;
            }
        }
        __syncwarp();

        // ---- O += P Vhi ; O += P Vlo  (V-side exact; independent chains)
#pragma unroll
        for (int ks = 0; ks < 8; ks++) {
            uint32_t a[4];
            int cc = ks * 8 + tg;
            a[0] = Pw[(g    ) * PSTR + cc    ];
            a[1] = Pw[(g + 8) * PSTR + cc    ];
            a[2] = Pw[(g    ) * PSTR + cc + 4];
            a[3] = Pw[(g + 8) * PSTR + cc + 4];
#pragma unroll
            for (int nt = 0; nt < 8; nt++) {
                int nr = nt * 8 + g;
                uint32_t bh0 = sVh[nr * PSTR + ks * 8 + tg    ];
                uint32_t bh1 = sVh[nr * PSTR + ks * 8 + tg + 4];
                mma_tf32(of[nt], a[0], a[1], a[2], a[3], bh0, bh1);
            }
#pragma unroll
            for (int nt = 0; nt < 8; nt++) {
                int nr = nt * 8 + g;
                uint32_t bl0 = sVl[nr * PSTR + ks * 8 + tg    ];
                uint32_t bl1 = sVl[nr * PSTR + ks * 8 + tg + 4];
                mma_tf32(of[nt], a[0], a[1], a[2], a[3], bl0, bl1);
            }
        }
        __syncwarp();
    }

    // ---- epilogue: O /= l, write [b][s][h*64+d]
    float* Og = O + ((size_t)(b * SS) + qbase) * DM + h * HDIM;
    {
        float inv0 = 1.0f / lrow[0];
        float inv1 = 1.0f / lrow[1];
        int r0 = w * 16 + g;
#pragma unroll
        for (int nt = 0; nt < 8; nt++) {
            int cc = nt * 8 + 2 * tg;
            *(float2*)&Og[(size_t)(r0    ) * DM + cc] =
                make_float2(of[nt][0] * inv0, of[nt][1] * inv0);
            *(float2*)&Og[(size_t)(r0 + 8) * DM + cc] =
                make_float2(of[nt][2] * inv1, of[nt][3] * inv1);
        }
    }
}

// ---------------------------------------------------------------------------
// kernel_launch
// ---------------------------------------------------------------------------
extern "C" void kernel_launch(void* const* d_in, const int* in_sizes, int n_in,
                              void* d_out, int out_size)
{
    const float* qx = (const float*)d_in[0];
    const float* kx = (const float*)d_in[1];
    const float* vx = (const float*)d_in[2];
    const float* Wq = (const float*)d_in[4];
    const float* bq = (const float*)d_in[5];
    const float* Wk = (const float*)d_in[6];
    const float* bk = (const float*)d_in[7];
    const float* Wv = (const float*)d_in[8];
    const float* bv = (const float*)d_in[9];
    float* out = (float*)d_out;

    uint32_t *gq, *gk, *gvh, *gvl;
    cudaGetSymbolAddress((void**)&gq,  g_qt);
    cudaGetSymbolAddress((void**)&gk,  g_kt);
    cudaGetSymbolAddress((void**)&gvh, g_vthi);
    cudaGetSymbolAddress((void**)&gvl, g_vtlo);

    dim3 ggrid(DM / BN, (BB * SS) / BM, 3);   // (16, 32, 3)
    gemm_fused<<<ggrid, 256>>>(qx, Wq, bq, kx, Wk, bk, vx, Wv, bv,
                               gq, gk, gvh, gvl);

    cudaFuncSetAttribute(flash_attn_tc,
                         cudaFuncAttributeMaxDynamicSharedMemorySize, FA_SMEM);
    dim3 agrid(SS / QT, NH, BB);    // (16, 16, 2)
    flash_attn_tc<<<agrid, 256, FA_SMEM>>>(gq, gk, gvh, gvl, out);
}

// round 13
// speedup vs baseline: 1.1069x; 1.1069x over previous
#include <cuda_runtime.h>
#include <math.h>
#include <stdint.h>

// Problem constants
#define BB   2
#define SS   2048
#define DM   1024
#define NH   16
#define HDIM 64

// Scratch (device globals: allocation-free)
__device__ uint32_t g_qt[BB * SS * DM];
__device__ uint32_t g_kt[BB * SS * DM];
__device__ uint32_t g_vthi[BB * NH * HDIM * SS];
__device__ uint32_t g_vtlo[BB * NH * HDIM * SS];

// ---------------------------------------------------------------------------
// Helpers
// ---------------------------------------------------------------------------
__device__ __forceinline__ void tf32_split(float x, uint32_t& hi, uint32_t& lo) {
    uint32_t xh = __float_as_uint(x) & 0xFFFFE000u;
    hi = xh;
    lo = __float_as_uint(x - __uint_as_float(xh));
}

__device__ __forceinline__ uint32_t cvt_tf32(float x) {
    uint32_t u;
    asm("cvt.rna.tf32.f32 %0, %1;" : "=r"(u) : "f"(x));
    return u;
}

__device__ __forceinline__ void mma_tf32(float* c,
                                         uint32_t a0, uint32_t a1, uint32_t a2, uint32_t a3,
                                         uint32_t b0, uint32_t b1) {
    asm volatile(
        "mma.sync.aligned.m16n8k8.row.col.f32.tf32.tf32.f32 "
        "{%0,%1,%2,%3}, {%4,%5,%6,%7}, {%8,%9}, {%0,%1,%2,%3};\n"
        : "+f"(c[0]), "+f"(c[1]), "+f"(c[2]), "+f"(c[3])
        : "r"(a0), "r"(a1), "r"(a2), "r"(a3), "r"(b0), "r"(b1));
}

__device__ __forceinline__ void cp_async16(void* smem, const void* gmem) {
    uint32_t s = (uint32_t)__cvta_generic_to_shared(smem);
    asm volatile("cp.async.ca.shared.global [%0], [%1], 16;\n" :: "r"(s), "l"(gmem));
}
__device__ __forceinline__ void cp_commit() {
    asm volatile("cp.async.commit_group;\n");
}
__device__ __forceinline__ void cp_wait1() {
    asm volatile("cp.async.wait_group 1;\n");
}
__device__ __forceinline__ void cp_wait0() {
    asm volatile("cp.async.wait_group 0;\n");
}

// ---------------------------------------------------------------------------
// Fused projection GEMMs: one launch, blockIdx.z selects {Q, K, V}.
// CTA tile 128x64, BK=16, 256 threads, warp 32x32, 3-stage cp.async pipeline.
//  z=0: Q -> tf32 out, scaled 1/32     (1-pass tf32)
//  z=1: K -> tf32 out                  (1-pass tf32)
//  z=2: V -> transposed split hi/lo    (2-pass: X 1-cvt, W split -> W-side exact)
// ---------------------------------------------------------------------------
#define BM 128
#define BN 64
#define BK 16
#define KPAD 4
#define NSTG 3

__device__ __forceinline__ void gemm_load_stage(
    const float* __restrict__ X, const float* __restrict__ W,
    float (*As)[BK + KPAD], float (*Bs)[BK + KPAD],
    int m0, int n0, int k0, int K, int tid)
{
#pragma unroll
    for (int i = 0; i < 2; i++) {
        int f   = tid + i * 256;
        int row = f >> 2;
        int kq  = (f & 3) * 4;
        cp_async16(&As[row][kq], &X[(size_t)(m0 + row) * K + k0 + kq]);
    }
    {
        int row = tid >> 2;
        int kq  = (tid & 3) * 4;
        cp_async16(&Bs[row][kq], &W[(size_t)(n0 + row) * K + k0 + kq]);
    }
    cp_commit();
}

__global__ __launch_bounds__(256) void gemm_fused(
    const float* __restrict__ qx, const float* __restrict__ Wq, const float* __restrict__ bq,
    const float* __restrict__ kx, const float* __restrict__ Wk, const float* __restrict__ bk,
    const float* __restrict__ vx, const float* __restrict__ Wv, const float* __restrict__ bv,
    uint32_t* __restrict__ YQ, uint32_t* __restrict__ YK,
    uint32_t* __restrict__ VHI, uint32_t* __restrict__ VLO)
{
    __shared__ __align__(16) float As[NSTG][BM][BK + KPAD];
    __shared__ __align__(16) float Bs[NSTG][BN][BK + KPAD];

    const int mode = blockIdx.z;
    const float* X    = (mode == 0) ? qx : (mode == 1) ? kx : vx;
    const float* W    = (mode == 0) ? Wq : (mode == 1) ? Wk : Wv;
    const float* bias = (mode == 0) ? bq : (mode == 1) ? bk : bv;

    const int tid  = threadIdx.x;
    const int warp = tid >> 5;
    const int lane = tid & 31;
    const int wm = (warp >> 1) * 32;
    const int wn = (warp & 1) * 32;
    const int g  = lane >> 2;
    const int tg = lane & 3;
    const int m0 = blockIdx.y * BM;
    const int n0 = blockIdx.x * BN;
    const int K = DM, N = DM;
    const int NIT = K / BK;

    float c[2][4][4];
#pragma unroll
    for (int mt = 0; mt < 2; mt++)
#pragma unroll
        for (int nt = 0; nt < 4; nt++)
#pragma unroll
            for (int r = 0; r < 4; r++) c[mt][nt][r] = 0.0f;

    gemm_load_stage(X, W, As[0], Bs[0], m0, n0, 0, K, tid);
    gemm_load_stage(X, W, As[1], Bs[1], m0, n0, BK, K, tid);

    for (int it = 0; it < NIT; it++) {
        if (it + 2 < NIT) cp_wait1(); else cp_wait0();
        __syncthreads();
        if (it + 2 < NIT)
            gemm_load_stage(X, W, As[(it + 2) % NSTG], Bs[(it + 2) % NSTG],
                            m0, n0, (it + 2) * BK, K, tid);

        const int st = it % NSTG;
        if (mode < 2) {
            // 1-pass tf32
#pragma unroll
            for (int ks = 0; ks < 2; ks++) {
                const int kb = ks * 8;
                uint32_t a[2][4];
#pragma unroll
                for (int mt = 0; mt < 2; mt++) {
                    int r0 = wm + mt * 16;
                    a[mt][0] = cvt_tf32(As[st][r0 + g    ][kb + tg    ]);
                    a[mt][1] = cvt_tf32(As[st][r0 + g + 8][kb + tg    ]);
                    a[mt][2] = cvt_tf32(As[st][r0 + g    ][kb + tg + 4]);
                    a[mt][3] = cvt_tf32(As[st][r0 + g + 8][kb + tg + 4]);
                }
#pragma unroll
                for (int nt = 0; nt < 4; nt++) {
                    int nr = wn + nt * 8 + g;
                    uint32_t b0 = cvt_tf32(Bs[st][nr][kb + tg    ]);
                    uint32_t b1 = cvt_tf32(Bs[st][nr][kb + tg + 4]);
#pragma unroll
                    for (int mt = 0; mt < 2; mt++)
                        mma_tf32(c[mt][nt], a[mt][0], a[mt][1], a[mt][2], a[mt][3], b0, b1);
                }
            }
        } else {
            // 2-pass: X single-cvt (A), W split (B) -> W-side exact
#pragma unroll
            for (int ks = 0; ks < 2; ks++) {
                const int kb = ks * 8;
                uint32_t a[2][4];
#pragma unroll
                for (int mt = 0; mt < 2; mt++) {
                    int r0 = wm + mt * 16;
                    a[mt][0] = cvt_tf32(As[st][r0 + g    ][kb + tg    ]);
                    a[mt][1] = cvt_tf32(As[st][r0 + g + 8][kb + tg    ]);
                    a[mt][2] = cvt_tf32(As[st][r0 + g    ][kb + tg + 4]);
                    a[mt][3] = cvt_tf32(As[st][r0 + g + 8][kb + tg + 4]);
                }
#pragma unroll
                for (int nt = 0; nt < 4; nt++) {
                    int nr = wn + nt * 8 + g;
                    uint32_t bh0, bl0, bh1, bl1;
                    tf32_split(Bs[st][nr][kb + tg    ], bh0, bl0);
                    tf32_split(Bs[st][nr][kb + tg + 4], bh1, bl1);
#pragma unroll
                    for (int mt = 0; mt < 2; mt++) {
                        mma_tf32(c[mt][nt], a[mt][0], a[mt][1], a[mt][2], a[mt][3], bh0, bh1);
                        mma_tf32(c[mt][nt], a[mt][0], a[mt][1], a[mt][2], a[mt][3], bl0, bl1);
                    }
                }
            }
        }
        __syncthreads();
    }

    if (mode < 2) {
        uint32_t* Y = (mode == 0) ? YQ : YK;
        const float oscale = (mode == 0) ? 0.03125f : 1.0f;
#pragma unroll
        for (int mt = 0; mt < 2; mt++) {
#pragma unroll
            for (int nt = 0; nt < 4; nt++) {
                int m = m0 + wm + mt * 16 + g;
                int n = n0 + wn + nt * 8 + tg * 2;
                float b0 = bias[n];
                float b1 = bias[n + 1];
                Y[(size_t)m * N + n]           = cvt_tf32((c[mt][nt][0] + b0) * oscale);
                Y[(size_t)m * N + n + 1]       = cvt_tf32((c[mt][nt][1] + b1) * oscale);
                Y[(size_t)(m + 8) * N + n]     = cvt_tf32((c[mt][nt][2] + b0) * oscale);
                Y[(size_t)(m + 8) * N + n + 1] = cvt_tf32((c[mt][nt][3] + b1) * oscale);
            }
        }
    } else {
        // Transposed + split epilogue: m=(b,s), n=(h,d) -> [((b*NH+h)*HDIM+d)*SS + s]
#pragma unroll
        for (int mt = 0; mt < 2; mt++) {
#pragma unroll
            for (int nt = 0; nt < 4; nt++) {
                int m = m0 + wm + mt * 16 + g;
                int n = n0 + wn + nt * 8 + tg * 2;
                int bidx = m >> 11, s = m & 2047;
#pragma unroll
                for (int e = 0; e < 2; e++) {
                    int nn = n + e;
                    int hh = nn >> 6, dd = nn & 63;
                    size_t base = (((size_t)(bidx * NH + hh)) * HDIM + dd) * SS;
                    float bb = bias[nn];
#pragma unroll
                    for (int rr = 0; rr < 2; rr++) {
                        float y = c[mt][nt][e + 2 * rr] + bb;
                        uint32_t hi = __float_as_uint(y) & 0xFFFFE000u;  // tf32-exact
                        float lo = y - __uint_as_float(hi);
                        VHI[base + s + 8 * rr] = hi;
                        VLO[base + s + 8 * rr] = cvt_tf32(lo);
                    }
                }
            }
        }
    }
}

// ---------------------------------------------------------------------------
// Tensor-core flash attention (TF32), causal.  (R7 configuration: 128 threads,
// 4 warps x 32 q-rows — measured-best warp<->row mapping.)
// ---------------------------------------------------------------------------
#define QT 128
#define KT 64
#define PSTR 68
#define FA_SMEM ((3 * 64 * PSTR + 4 * 32 * PSTR) * (int)sizeof(uint32_t))

__global__ __launch_bounds__(128) void flash_attn_tc(
    const uint32_t* __restrict__ Qt, const uint32_t* __restrict__ Kt,
    const uint32_t* __restrict__ VHI, const uint32_t* __restrict__ VLO,
    float* __restrict__ O)
{
    extern __shared__ uint32_t smu[];
    uint32_t* sK  = smu;
    uint32_t* sVh = smu + 64 * PSTR;
    uint32_t* sVl = smu + 2 * 64 * PSTR;
    uint32_t* sP  = smu + 3 * 64 * PSTR;

    const int tid  = threadIdx.x;
    const int w    = tid >> 5;
    const int lane = tid & 31;
    const int g    = lane >> 2;
    const int tg   = lane & 3;
    const int qt   = (int)gridDim.x - 1 - (int)blockIdx.x;
    const int h    = blockIdx.y;
    const int b    = blockIdx.z;
    const int qbase = qt * QT;
    const float NEG = -1.0e30f;

    const uint32_t* Qg = Qt + ((size_t)(b * SS) + qbase) * DM + h * HDIM;
    uint32_t qf[2][8][4];
#pragma unroll
    for (int mt = 0; mt < 2; mt++) {
        int r0 = w * 32 + mt * 16 + g;
#pragma unroll
        for (int ks = 0; ks < 8; ks++) {
            int cc = ks * 8 + tg;
            qf[mt][ks][0] = Qg[(size_t)(r0    ) * DM + cc    ];
            qf[mt][ks][1] = Qg[(size_t)(r0 + 8) * DM + cc    ];
            qf[mt][ks][2] = Qg[(size_t)(r0    ) * DM + cc + 4];
            qf[mt][ks][3] = Qg[(size_t)(r0 + 8) * DM + cc + 4];
        }
    }

    float of[2][8][4];
    float mrow[2][2], lrow[2][2];
#pragma unroll
    for (int mt = 0; mt < 2; mt++) {
        mrow[mt][0] = NEG; mrow[mt][1] = NEG;
        lrow[mt][0] = 0.f; lrow[mt][1] = 0.f;
#pragma unroll
        for (int nt = 0; nt < 8; nt++)
#pragma unroll
            for (int r = 0; r < 4; r++) of[mt][nt][r] = 0.f;
    }

    uint32_t* Pw = sP + w * 32 * PSTR;
    const int nkt = 2 * qt + 2;

    for (int kt = 0; kt < nkt; kt++) {
        __syncthreads();
        const uint32_t* Kg = Kt  + ((size_t)(b * SS) + kt * KT) * DM + h * HDIM;
        size_t vbase = ((size_t)(b * NH + h) * HDIM) * SS + kt * KT;
#pragma unroll
        for (int i = 0; i < 8; i++) {
            int f = tid + i * 128;
            int row = f >> 4, c4 = (f & 15) * 4;
            *(uint4*)&sK[row * PSTR + c4]  = *(const uint4*)&Kg[(size_t)row * DM + c4];
            *(uint4*)&sVh[row * PSTR + c4] = *(const uint4*)&VHI[vbase + (size_t)row * SS + c4];
            *(uint4*)&sVl[row * PSTR + c4] = *(const uint4*)&VLO[vbase + (size_t)row * SS + c4];
        }
        __syncthreads();

        if (kt * KT > qbase + w * 32 + 31) continue;

        float s[2][8][4];
#pragma unroll
        for (int mt = 0; mt < 2; mt++)
#pragma unroll
            for (int nt = 0; nt < 8; nt++)
#pragma unroll
                for (int r = 0; r < 4; r++) s[mt][nt][r] = 0.f;

#pragma unroll
        for (int ks = 0; ks < 8; ks++) {
#pragma unroll
            for (int nt = 0; nt < 8; nt++) {
                int nr = nt * 8 + g;
                uint32_t b0 = sK[nr * PSTR + ks * 8 + tg    ];
                uint32_t b1 = sK[nr * PSTR + ks * 8 + tg + 4];
                mma_tf32(s[0][nt], qf[0][ks][0], qf[0][ks][1], qf[0][ks][2], qf[0][ks][3], b0, b1);
                mma_tf32(s[1][nt], qf[1][ks][0], qf[1][ks][1], qf[1][ks][2], qf[1][ks][3], b0, b1);
            }
        }

        if (kt >= 2 * qt) {
#pragma unroll
            for (int mt = 0; mt < 2; mt++) {
                int row0 = qbase + w * 32 + mt * 16 + g;
#pragma unroll
                for (int nt = 0; nt < 8; nt++) {
                    int col = kt * KT + nt * 8 + 2 * tg;
                    if (col     > row0    ) s[mt][nt][0] = NEG;
                    if (col + 1 > row0    ) s[mt][nt][1] = NEG;
                    if (col     > row0 + 8) s[mt][nt][2] = NEG;
                    if (col + 1 > row0 + 8) s[mt][nt][3] = NEG;
                }
            }
        }

#pragma unroll
        for (int mt = 0; mt < 2; mt++) {
            float rm0 = NEG, rm1 = NEG;
#pragma unroll
            for (int nt = 0; nt < 8; nt++) {
                rm0 = fmaxf(rm0, fmaxf(s[mt][nt][0], s[mt][nt][1]));
                rm1 = fmaxf(rm1, fmaxf(s[mt][nt][2], s[mt][nt][3]));
            }
#pragma unroll
            for (int d = 1; d < 4; d <<= 1) {
                rm0 = fmaxf(rm0, __shfl_xor_sync(0xffffffffu, rm0, d));
                rm1 = fmaxf(rm1, __shfl_xor_sync(0xffffffffu, rm1, d));
            }
            float mn0 = fmaxf(mrow[mt][0], rm0);
            float mn1 = fmaxf(mrow[mt][1], rm1);
            float corr0 = __expf(mrow[mt][0] - mn0);
            float corr1 = __expf(mrow[mt][1] - mn1);
            float rs0 = 0.f, rs1 = 0.f;
#pragma unroll
            for (int nt = 0; nt < 8; nt++) {
                s[mt][nt][0] = __expf(s[mt][nt][0] - mn0);
                s[mt][nt][1] = __expf(s[mt][nt][1] - mn0);
                s[mt][nt][2] = __expf(s[mt][nt][2] - mn1);
                s[mt][nt][3] = __expf(s[mt][nt][3] - mn1);
                rs0 += s[mt][nt][0] + s[mt][nt][1];
                rs1 += s[mt][nt][2] + s[mt][nt][3];
            }
#pragma unroll
            for (int d = 1; d < 4; d <<= 1) {
                rs0 += __shfl_xor_sync(0xffffffffu, rs0, d);
                rs1 += __shfl_xor_sync(0xffffffffu, rs1, d);
            }
            lrow[mt][0] = lrow[mt][0] * corr0 + rs0;
            lrow[mt][1] = lrow[mt][1] * corr1 + rs1;
            mrow[mt][0] = mn0;
            mrow[mt][1] = mn1;
#pragma unroll
            for (int nt = 0; nt < 8; nt++) {
                of[mt][nt][0] *= corr0;
                of[mt][nt][1] *= corr0;
                of[mt][nt][2] *= corr1;
                of[mt][nt][3] *= corr1;
            }
            int pr = mt * 16 + g;
#pragma unroll
            for (int nt = 0; nt < 8; nt++) {
                uint2 p01 = make_uint2(cvt_tf32(s[mt][nt][0]), cvt_tf32(s[mt][nt][1]));
                uint2 p23 = make_uint2(cvt_tf32(s[mt][nt][2]), cvt_tf32(s[mt][nt][3]));
                *(uint2*)&Pw[(pr    ) * PSTR + nt * 8 + 2 * tg] = p01;
                *(uint2*)&Pw[(pr + 8) * PSTR + nt * 8 + 2 * tg] = p23;
            }
        }
        __syncwarp();

#pragma unroll
        for (int ks = 0; ks < 8; ks++) {
            uint32_t a[2][4];
#pragma unroll
            for (int mt = 0; mt < 2; mt++) {
                int pr = mt * 16 + g;
                int cc = ks * 8 + tg;
                a[mt][0] = Pw[(pr    ) * PSTR + cc    ];
                a[mt][1] = Pw[(pr + 8) * PSTR + cc    ];
                a[mt][2] = Pw[(pr    ) * PSTR + cc + 4];
                a[mt][3] = Pw[(pr + 8) * PSTR + cc + 4];
            }
#pragma unroll
            for (int nt = 0; nt < 8; nt++) {
                int nr = nt * 8 + g;
                uint32_t bh0 = sVh[nr * PSTR + ks * 8 + tg    ];
                uint32_t bh1 = sVh[nr * PSTR + ks * 8 + tg + 4];
                uint32_t bl0 = sVl[nr * PSTR + ks * 8 + tg    ];
                uint32_t bl1 = sVl[nr * PSTR + ks * 8 + tg + 4];
#pragma unroll
                for (int mt = 0; mt < 2; mt++) {
                    mma_tf32(of[mt][nt], a[mt][0], a[mt][1], a[mt][2], a[mt][3], bh0, bh1);
                    mma_tf32(of[mt][nt], a[mt][0], a[mt][1], a[mt][2], a[mt][3], bl0, bl1);
                }
            }
        }
        __syncwarp();
    }

    float* Og = O + ((size_t)(b * SS) + qbase) * DM + h * HDIM;
#pragma unroll
    for (int mt = 0; mt < 2; mt++) {
        float inv0 = 1.0f / lrow[mt][0];
        float inv1 = 1.0f / lrow[mt][1];
        int r0 = w * 32 + mt * 16 + g;
#pragma unroll
        for (int nt = 0; nt < 8; nt++) {
            int cc = nt * 8 + 2 * tg;
            *(float2*)&Og[(size_t)(r0    ) * DM + cc] =
                make_float2(of[mt][nt][0] * inv0, of[mt][nt][1] * inv0);
            *(float2*)&Og[(size_t)(r0 + 8) * DM + cc] =
                make_float2(of[mt][nt][2] * inv1, of[mt][nt][3] * inv1);
        }
    }
}

// ---------------------------------------------------------------------------
// kernel_launch
// ---------------------------------------------------------------------------
extern "C" void kernel_launch(void* const* d_in, const int* in_sizes, int n_in,
                              void* d_out, int out_size)
{
    const float* qx = (const float*)d_in[0];
    const float* kx = (const float*)d_in[1];
    const float* vx = (const float*)d_in[2];
    const float* Wq = (const float*)d_in[4];
    const float* bq = (const float*)d_in[5];
    const float* Wk = (const float*)d_in[6];
    const float* bk = (const float*)d_in[7];
    const float* Wv = (const float*)d_in[8];
    const float* bv = (const float*)d_in[9];
    float* out = (float*)d_out;

    uint32_t *gq, *gk, *gvh, *gvl;
    cudaGetSymbolAddress((void**)&gq,  g_qt);
    cudaGetSymbolAddress((void**)&gk,  g_kt);
    cudaGetSymbolAddress((void**)&gvh, g_vthi);
    cudaGetSymbolAddress((void**)&gvl, g_vtlo);

    dim3 ggrid(DM / BN, (BB * SS) / BM, 3);   // (16, 32, 3)
    gemm_fused<<<ggrid, 256>>>(qx, Wq, bq, kx, Wk, bk, vx, Wv, bv,
                               gq, gk, gvh, gvl);

    cudaFuncSetAttribute(flash_attn_tc,
                         cudaFuncAttributeMaxDynamicSharedMemorySize, FA_SMEM);
    dim3 agrid(SS / QT, NH, BB);    // (16, 16, 2)
    flash_attn_tc<<<agrid, 128, FA_SMEM>>>(gq, gk, gvh, gvl, out);
}

// round 14
// speedup vs baseline: 1.2632x; 1.1412x over previous
#include <cuda_runtime.h>
#include <math.h>
#include <stdint.h>

// Problem constants
#define BB   2
#define SS   2048
#define DM   1024
#define NH   16
#define HDIM 64

// Scratch (device globals: allocation-free)
__device__ uint32_t g_qt[BB * SS * DM];
__device__ uint32_t g_kt[BB * SS * DM];
__device__ uint32_t g_vt[BB * NH * HDIM * SS];   // V^T as single tf32 plane

// ---------------------------------------------------------------------------
// Helpers
// ---------------------------------------------------------------------------
__device__ __forceinline__ void tf32_split(float x, uint32_t& hi, uint32_t& lo) {
    uint32_t xh = __float_as_uint(x) & 0xFFFFE000u;
    hi = xh;
    lo = __float_as_uint(x - __uint_as_float(xh));
}

__device__ __forceinline__ uint32_t cvt_tf32(float x) {
    uint32_t u;
    asm("cvt.rna.tf32.f32 %0, %1;" : "=r"(u) : "f"(x));
    return u;
}

__device__ __forceinline__ void mma_tf32(float* c,
                                         uint32_t a0, uint32_t a1, uint32_t a2, uint32_t a3,
                                         uint32_t b0, uint32_t b1) {
    asm volatile(
        "mma.sync.aligned.m16n8k8.row.col.f32.tf32.tf32.f32 "
        "{%0,%1,%2,%3}, {%4,%5,%6,%7}, {%8,%9}, {%0,%1,%2,%3};\n"
        : "+f"(c[0]), "+f"(c[1]), "+f"(c[2]), "+f"(c[3])
        : "r"(a0), "r"(a1), "r"(a2), "r"(a3), "r"(b0), "r"(b1));
}

__device__ __forceinline__ void cp_async16(void* smem, const void* gmem) {
    uint32_t s = (uint32_t)__cvta_generic_to_shared(smem);
    asm volatile("cp.async.ca.shared.global [%0], [%1], 16;\n" :: "r"(s), "l"(gmem));
}
__device__ __forceinline__ void cp_commit() {
    asm volatile("cp.async.commit_group;\n");
}
__device__ __forceinline__ void cp_wait1() {
    asm volatile("cp.async.wait_group 1;\n");
}
__device__ __forceinline__ void cp_wait0() {
    asm volatile("cp.async.wait_group 0;\n");
}

// ---------------------------------------------------------------------------
// Fused projection GEMMs: one launch, blockIdx.z selects {Q, K, V}.
// CTA tile 128x64, BK=16, 256 threads, warp 32x32, 3-stage cp.async pipeline.
//  z=0: Q -> tf32 out, scaled 1/32     (1-pass tf32)
//  z=1: K -> tf32 out                  (1-pass tf32)
//  z=2: V -> transposed tf32 out       (2-pass compute: W-side exact; single store)
// ---------------------------------------------------------------------------
#define BM 128
#define BN 64
#define BK 16
#define KPAD 4
#define NSTG 3

__device__ __forceinline__ void gemm_load_stage(
    const float* __restrict__ X, const float* __restrict__ W,
    float (*As)[BK + KPAD], float (*Bs)[BK + KPAD],
    int m0, int n0, int k0, int K, int tid)
{
#pragma unroll
    for (int i = 0; i < 2; i++) {
        int f   = tid + i * 256;
        int row = f >> 2;
        int kq  = (f & 3) * 4;
        cp_async16(&As[row][kq], &X[(size_t)(m0 + row) * K + k0 + kq]);
    }
    {
        int row = tid >> 2;
        int kq  = (tid & 3) * 4;
        cp_async16(&Bs[row][kq], &W[(size_t)(n0 + row) * K + k0 + kq]);
    }
    cp_commit();
}

__global__ __launch_bounds__(256) void gemm_fused(
    const float* __restrict__ qx, const float* __restrict__ Wq, const float* __restrict__ bq,
    const float* __restrict__ kx, const float* __restrict__ Wk, const float* __restrict__ bk,
    const float* __restrict__ vx, const float* __restrict__ Wv, const float* __restrict__ bv,
    uint32_t* __restrict__ YQ, uint32_t* __restrict__ YK,
    uint32_t* __restrict__ VT)
{
    __shared__ __align__(16) float As[NSTG][BM][BK + KPAD];
    __shared__ __align__(16) float Bs[NSTG][BN][BK + KPAD];

    const int mode = blockIdx.z;
    const float* X    = (mode == 0) ? qx : (mode == 1) ? kx : vx;
    const float* W    = (mode == 0) ? Wq : (mode == 1) ? Wk : Wv;
    const float* bias = (mode == 0) ? bq : (mode == 1) ? bk : bv;

    const int tid  = threadIdx.x;
    const int warp = tid >> 5;
    const int lane = tid & 31;
    const int wm = (warp >> 1) * 32;
    const int wn = (warp & 1) * 32;
    const int g  = lane >> 2;
    const int tg = lane & 3;
    const int m0 = blockIdx.y * BM;
    const int n0 = blockIdx.x * BN;
    const int K = DM, N = DM;
    const int NIT = K / BK;

    float c[2][4][4];
#pragma unroll
    for (int mt = 0; mt < 2; mt++)
#pragma unroll
        for (int nt = 0; nt < 4; nt++)
#pragma unroll
            for (int r = 0; r < 4; r++) c[mt][nt][r] = 0.0f;

    gemm_load_stage(X, W, As[0], Bs[0], m0, n0, 0, K, tid);
    gemm_load_stage(X, W, As[1], Bs[1], m0, n0, BK, K, tid);

    for (int it = 0; it < NIT; it++) {
        if (it + 2 < NIT) cp_wait1(); else cp_wait0();
        __syncthreads();
        if (it + 2 < NIT)
            gemm_load_stage(X, W, As[(it + 2) % NSTG], Bs[(it + 2) % NSTG],
                            m0, n0, (it + 2) * BK, K, tid);

        const int st = it % NSTG;
        if (mode < 2) {
            // 1-pass tf32
#pragma unroll
            for (int ks = 0; ks < 2; ks++) {
                const int kb = ks * 8;
                uint32_t a[2][4];
#pragma unroll
                for (int mt = 0; mt < 2; mt++) {
                    int r0 = wm + mt * 16;
                    a[mt][0] = cvt_tf32(As[st][r0 + g    ][kb + tg    ]);
                    a[mt][1] = cvt_tf32(As[st][r0 + g + 8][kb + tg    ]);
                    a[mt][2] = cvt_tf32(As[st][r0 + g    ][kb + tg + 4]);
                    a[mt][3] = cvt_tf32(As[st][r0 + g + 8][kb + tg + 4]);
                }
#pragma unroll
                for (int nt = 0; nt < 4; nt++) {
                    int nr = wn + nt * 8 + g;
                    uint32_t b0 = cvt_tf32(Bs[st][nr][kb + tg    ]);
                    uint32_t b1 = cvt_tf32(Bs[st][nr][kb + tg + 4]);
#pragma unroll
                    for (int mt = 0; mt < 2; mt++)
                        mma_tf32(c[mt][nt], a[mt][0], a[mt][1], a[mt][2], a[mt][3], b0, b1);
                }
            }
        } else {
            // 2-pass: X single-cvt (A), W split (B) -> W-side exact
#pragma unroll
            for (int ks = 0; ks < 2; ks++) {
                const int kb = ks * 8;
                uint32_t a[2][4];
#pragma unroll
                for (int mt = 0; mt < 2; mt++) {
                    int r0 = wm + mt * 16;
                    a[mt][0] = cvt_tf32(As[st][r0 + g    ][kb + tg    ]);
                    a[mt][1] = cvt_tf32(As[st][r0 + g + 8][kb + tg    ]);
                    a[mt][2] = cvt_tf32(As[st][r0 + g    ][kb + tg + 4]);
                    a[mt][3] = cvt_tf32(As[st][r0 + g + 8][kb + tg + 4]);
                }
#pragma unroll
                for (int nt = 0; nt < 4; nt++) {
                    int nr = wn + nt * 8 + g;
                    uint32_t bh0, bl0, bh1, bl1;
                    tf32_split(Bs[st][nr][kb + tg    ], bh0, bl0);
                    tf32_split(Bs[st][nr][kb + tg + 4], bh1, bl1);
#pragma unroll
                    for (int mt = 0; mt < 2; mt++) {
                        mma_tf32(c[mt][nt], a[mt][0], a[mt][1], a[mt][2], a[mt][3], bh0, bh1);
                        mma_tf32(c[mt][nt], a[mt][0], a[mt][1], a[mt][2], a[mt][3], bl0, bl1);
                    }
                }
            }
        }
        __syncthreads();
    }

    if (mode < 2) {
        uint32_t* Y = (mode == 0) ? YQ : YK;
        const float oscale = (mode == 0) ? 0.03125f : 1.0f;
#pragma unroll
        for (int mt = 0; mt < 2; mt++) {
#pragma unroll
            for (int nt = 0; nt < 4; nt++) {
                int m = m0 + wm + mt * 16 + g;
                int n = n0 + wn + nt * 8 + tg * 2;
                float b0 = bias[n];
                float b1 = bias[n + 1];
                Y[(size_t)m * N + n]           = cvt_tf32((c[mt][nt][0] + b0) * oscale);
                Y[(size_t)m * N + n + 1]       = cvt_tf32((c[mt][nt][1] + b1) * oscale);
                Y[(size_t)(m + 8) * N + n]     = cvt_tf32((c[mt][nt][2] + b0) * oscale);
                Y[(size_t)(m + 8) * N + n + 1] = cvt_tf32((c[mt][nt][3] + b1) * oscale);
            }
        }
    } else {
        // Transposed epilogue: m=(b,s), n=(h,d) -> VT[((b*NH+h)*HDIM+d)*SS + s], tf32
#pragma unroll
        for (int mt = 0; mt < 2; mt++) {
#pragma unroll
            for (int nt = 0; nt < 4; nt++) {
                int m = m0 + wm + mt * 16 + g;
                int n = n0 + wn + nt * 8 + tg * 2;
                int bidx = m >> 11, s = m & 2047;
#pragma unroll
                for (int e = 0; e < 2; e++) {
                    int nn = n + e;
                    int hh = nn >> 6, dd = nn & 63;
                    size_t base = (((size_t)(bidx * NH + hh)) * HDIM + dd) * SS;
                    float bb = bias[nn];
                    VT[base + s]     = cvt_tf32(c[mt][nt][e]     + bb);
                    VT[base + s + 8] = cvt_tf32(c[mt][nt][e + 2] + bb);
                }
            }
        }
    }
}

// ---------------------------------------------------------------------------
// Tensor-core flash attention (TF32), causal.  128 threads, 4 warps x 32 q-rows
// (measured-best mapping).  P*V single-pass tf32 (V pre-rounded to tf32).
// ---------------------------------------------------------------------------
#define QT 128
#define KT 64
#define PSTR 68
#define FA_SMEM ((2 * 64 * PSTR + 4 * 32 * PSTR) * (int)sizeof(uint32_t))

__global__ __launch_bounds__(128) void flash_attn_tc(
    const uint32_t* __restrict__ Qt, const uint32_t* __restrict__ Kt,
    const uint32_t* __restrict__ VT, float* __restrict__ O)
{
    extern __shared__ uint32_t smu[];
    uint32_t* sK = smu;                  // K tile [64 keys][PSTR] (cols = d)
    uint32_t* sV = smu + 64 * PSTR;      // V^T tile [64 d][PSTR]  (cols = key)
    uint32_t* sP = smu + 2 * 64 * PSTR;  // per-warp P [32][PSTR]

    const int tid  = threadIdx.x;
    const int w    = tid >> 5;
    const int lane = tid & 31;
    const int g    = lane >> 2;
    const int tg   = lane & 3;
    const int qt   = (int)gridDim.x - 1 - (int)blockIdx.x;
    const int h    = blockIdx.y;
    const int b    = blockIdx.z;
    const int qbase = qt * QT;
    const float NEG = -1.0e30f;

    const uint32_t* Qg = Qt + ((size_t)(b * SS) + qbase) * DM + h * HDIM;
    uint32_t qf[2][8][4];
#pragma unroll
    for (int mt = 0; mt < 2; mt++) {
        int r0 = w * 32 + mt * 16 + g;
#pragma unroll
        for (int ks = 0; ks < 8; ks++) {
            int cc = ks * 8 + tg;
            qf[mt][ks][0] = Qg[(size_t)(r0    ) * DM + cc    ];
            qf[mt][ks][1] = Qg[(size_t)(r0 + 8) * DM + cc    ];
            qf[mt][ks][2] = Qg[(size_t)(r0    ) * DM + cc + 4];
            qf[mt][ks][3] = Qg[(size_t)(r0 + 8) * DM + cc + 4];
        }
    }

    float of[2][8][4];
    float mrow[2][2], lrow[2][2];
#pragma unroll
    for (int mt = 0; mt < 2; mt++) {
        mrow[mt][0] = NEG; mrow[mt][1] = NEG;
        lrow[mt][0] = 0.f; lrow[mt][1] = 0.f;
#pragma unroll
        for (int nt = 0; nt < 8; nt++)
#pragma unroll
            for (int r = 0; r < 4; r++) of[mt][nt][r] = 0.f;
    }

    uint32_t* Pw = sP + w * 32 * PSTR;
    const int nkt = 2 * qt + 2;

    for (int kt = 0; kt < nkt; kt++) {
        __syncthreads();
        const uint32_t* Kg = Kt + ((size_t)(b * SS) + kt * KT) * DM + h * HDIM;
        size_t vbase = ((size_t)(b * NH + h) * HDIM) * SS + kt * KT;
#pragma unroll
        for (int i = 0; i < 8; i++) {
            int f = tid + i * 128;
            int row = f >> 4, c4 = (f & 15) * 4;
            *(uint4*)&sK[row * PSTR + c4] = *(const uint4*)&Kg[(size_t)row * DM + c4];
            *(uint4*)&sV[row * PSTR + c4] = *(const uint4*)&VT[vbase + (size_t)row * SS + c4];
        }
        __syncthreads();

        if (kt * KT > qbase + w * 32 + 31) continue;

        float s[2][8][4];
#pragma unroll
        for (int mt = 0; mt < 2; mt++)
#pragma unroll
            for (int nt = 0; nt < 8; nt++)
#pragma unroll
                for (int r = 0; r < 4; r++) s[mt][nt][r] = 0.f;

#pragma unroll
        for (int ks = 0; ks < 8; ks++) {
#pragma unroll
            for (int nt = 0; nt < 8; nt++) {
                int nr = nt * 8 + g;
                uint32_t b0 = sK[nr * PSTR + ks * 8 + tg    ];
                uint32_t b1 = sK[nr * PSTR + ks * 8 + tg + 4];
                mma_tf32(s[0][nt], qf[0][ks][0], qf[0][ks][1], qf[0][ks][2], qf[0][ks][3], b0, b1);
                mma_tf32(s[1][nt], qf[1][ks][0], qf[1][ks][1], qf[1][ks][2], qf[1][ks][3], b0, b1);
            }
        }

        if (kt >= 2 * qt) {
#pragma unroll
            for (int mt = 0; mt < 2; mt++) {
                int row0 = qbase + w * 32 + mt * 16 + g;
#pragma unroll
                for (int nt = 0; nt < 8; nt++) {
                    int col = kt * KT + nt * 8 + 2 * tg;
                    if (col     > row0    ) s[mt][nt][0] = NEG;
                    if (col + 1 > row0    ) s[mt][nt][1] = NEG;
                    if (col     > row0 + 8) s[mt][nt][2] = NEG;
                    if (col + 1 > row0 + 8) s[mt][nt][3] = NEG;
                }
            }
        }

#pragma unroll
        for (int mt = 0; mt < 2; mt++) {
            float rm0 = NEG, rm1 = NEG;
#pragma unroll
            for (int nt = 0; nt < 8; nt++) {
                rm0 = fmaxf(rm0, fmaxf(s[mt][nt][0], s[mt][nt][1]));
                rm1 = fmaxf(rm1, fmaxf(s[mt][nt][2], s[mt][nt][3]));
            }
#pragma unroll
            for (int d = 1; d < 4; d <<= 1) {
                rm0 = fmaxf(rm0, __shfl_xor_sync(0xffffffffu, rm0, d));
                rm1 = fmaxf(rm1, __shfl_xor_sync(0xffffffffu, rm1, d));
            }
            float mn0 = fmaxf(mrow[mt][0], rm0);
            float mn1 = fmaxf(mrow[mt][1], rm1);
            float corr0 = __expf(mrow[mt][0] - mn0);
            float corr1 = __expf(mrow[mt][1] - mn1);
            float rs0 = 0.f, rs1 = 0.f;
#pragma unroll
            for (int nt = 0; nt < 8; nt++) {
                s[mt][nt][0] = __expf(s[mt][nt][0] - mn0);
                s[mt][nt][1] = __expf(s[mt][nt][1] - mn0);
                s[mt][nt][2] = __expf(s[mt][nt][2] - mn1);
                s[mt][nt][3] = __expf(s[mt][nt][3] - mn1);
                rs0 += s[mt][nt][0] + s[mt][nt][1];
                rs1 += s[mt][nt][2] + s[mt][nt][3];
            }
#pragma unroll
            for (int d = 1; d < 4; d <<= 1) {
                rs0 += __shfl_xor_sync(0xffffffffu, rs0, d);
                rs1 += __shfl_xor_sync(0xffffffffu, rs1, d);
            }
            lrow[mt][0] = lrow[mt][0] * corr0 + rs0;
            lrow[mt][1] = lrow[mt][1] * corr1 + rs1;
            mrow[mt][0] = mn0;
            mrow[mt][1] = mn1;
#pragma unroll
            for (int nt = 0; nt < 8; nt++) {
                of[mt][nt][0] *= corr0;
                of[mt][nt][1] *= corr0;
                of[mt][nt][2] *= corr1;
                of[mt][nt][3] *= corr1;
            }
            int pr = mt * 16 + g;
#pragma unroll
            for (int nt = 0; nt < 8; nt++) {
                uint2 p01 = make_uint2(cvt_tf32(s[mt][nt][0]), cvt_tf32(s[mt][nt][1]));
                uint2 p23 = make_uint2(cvt_tf32(s[mt][nt][2]), cvt_tf32(s[mt][nt][3]));
                *(uint2*)&Pw[(pr    ) * PSTR + nt * 8 + 2 * tg] = p01;
                *(uint2*)&Pw[(pr + 8) * PSTR + nt * 8 + 2 * tg] = p23;
            }
        }
        __syncwarp();

        // ---- O += P V (single-pass tf32)
#pragma unroll
        for (int ks = 0; ks < 8; ks++) {
            uint32_t a[2][4];
#pragma unroll
            for (int mt = 0; mt < 2; mt++) {
                int pr = mt * 16 + g;
                int cc = ks * 8 + tg;
                a[mt][0] = Pw[(pr    ) * PSTR + cc    ];
                a[mt][1] = Pw[(pr + 8) * PSTR + cc    ];
                a[mt][2] = Pw[(pr    ) * PSTR + cc + 4];
                a[mt][3] = Pw[(pr + 8) * PSTR + cc + 4];
            }
#pragma unroll
            for (int nt = 0; nt < 8; nt++) {
                int nr = nt * 8 + g;
                uint32_t b0 = sV[nr * PSTR + ks * 8 + tg    ];
                uint32_t b1 = sV[nr * PSTR + ks * 8 + tg + 4];
#pragma unroll
                for (int mt = 0; mt < 2; mt++)
                    mma_tf32(of[mt][nt], a[mt][0], a[mt][1], a[mt][2], a[mt][3], b0, b1);
            }
        }
        __syncwarp();
    }

    float* Og = O + ((size_t)(b * SS) + qbase) * DM + h * HDIM;
#pragma unroll
    for (int mt = 0; mt < 2; mt++) {
        float inv0 = 1.0f / lrow[mt][0];
        float inv1 = 1.0f / lrow[mt][1];
        int r0 = w * 32 + mt * 16 + g;
#pragma unroll
        for (int nt = 0; nt < 8; nt++) {
            int cc = nt * 8 + 2 * tg;
            *(float2*)&Og[(size_t)(r0    ) * DM + cc] =
                make_float2(of[mt][nt][0] * inv0, of[mt][nt][1] * inv0);
            *(float2*)&Og[(size_t)(r0 + 8) * DM + cc] =
                make_float2(of[mt][nt][2] * inv1, of[mt][nt][3] * inv1);
        }
    }
}

// ---------------------------------------------------------------------------
// kernel_launch
// ---------------------------------------------------------------------------
extern "C" void kernel_launch(void* const* d_in, const int* in_sizes, int n_in,
                              void* d_out, int out_size)
{
    const float* qx = (const float*)d_in[0];
    const float* kx = (const float*)d_in[1];
    const float* vx = (const float*)d_in[2];
    const float* Wq = (const float*)d_in[4];
    const float* bq = (const float*)d_in[5];
    const float* Wk = (const float*)d_in[6];
    const float* bk = (const float*)d_in[7];
    const float* Wv = (const float*)d_in[8];
    const float* bv = (const float*)d_in[9];
    float* out = (float*)d_out;

    uint32_t *gq, *gk, *gv;
    cudaGetSymbolAddress((void**)&gq, g_qt);
    cudaGetSymbolAddress((void**)&gk, g_kt);
    cudaGetSymbolAddress((void**)&gv, g_vt);

    dim3 ggrid(DM / BN, (BB * SS) / BM, 3);   // (16, 32, 3)
    gemm_fused<<<ggrid, 256>>>(qx, Wq, bq, kx, Wk, bk, vx, Wv, bv,
                               gq, gk, gv);

    cudaFuncSetAttribute(flash_attn_tc,
                         cudaFuncAttributeMaxDynamicSharedMemorySize, FA_SMEM);
    dim3 agrid(SS / QT, NH, BB);    // (16, 16, 2)
    flash_attn_tc<<<agrid, 128, FA_SMEM>>>(gq, gk, gv, out);
}